// round 11
// baseline (speedup 1.0000x reference)
#include <cuda_runtime.h>
#include <cuda_bf16.h>
#include <cstdint>

#define BATCH   512
#define NACT    256
#define ENT_D   256
#define REL_D   256
#define HIST_D  512
#define ACT_DIM 512
#define IN_DIM  1024
#define HUGE_F  1e31f
#define EPS_F   1e-20f

// Scratch (referenced only inside device code)
__device__ float g_H [BATCH * ACT_DIM];
__device__ float g_X2[BATCH * ACT_DIM];
__device__ float g_SC[BATCH * NACT];

__device__ __forceinline__ float to_tf32(float x) {
    uint32_t u;
    asm("cvt.rna.tf32.f32 %0, %1;" : "=r"(u) : "f"(x));
    return __uint_as_float(u);
}

// ---------------------------------------------------------------------------
// GEMM: C = act(A @ W + bias), tf32 mma, double-buffered register prefetch.
// 256 thr (8 warps), block tile 32x64, warp tile 16x16, BK=32, grid 8x16.
// FIRST: A row = virtual concat [ent_emb[cur]|hist|rel_emb[qr]] (K=1024),
//        and each thread ALSO issues L2 prefetches for the ent-row gather
//        that scores_kernel will do later (131072 rows / 32768 threads).
// ---------------------------------------------------------------------------
template <int K, bool FIRST>
__global__ void mma_gemm_kernel(const float* __restrict__ W,
                                const float* __restrict__ bias,
                                const int* __restrict__ cur,
                                const int* __restrict__ qr,
                                const float* __restrict__ hist,
                                const float* __restrict__ ent_emb,
                                const float* __restrict__ rel_emb,
                                const int* __restrict__ e_space) {
    float* C = FIRST ? (float*)g_H : (float*)g_X2;
    const int N = ACT_DIM;

    __shared__ float As[2][32][36];
    __shared__ float Bs[2][32][72];

    int tid   = threadIdx.x;
    int warp  = tid >> 5;
    int lane  = tid & 31;
    int group = lane >> 2;
    int tig   = lane & 3;

    int brow   = blockIdx.y * 32;
    int bcol   = blockIdx.x * 64;
    int warp_m = (warp >> 2) * 16;
    int warp_n = (warp & 3)  * 16;

    // --- L2 prefetch of the ent gather rows scores_kernel will need ---
    if (FIRST) {
        int g = (blockIdx.y * gridDim.x + blockIdx.x) * 256 + tid;   // 0..32767
#pragma unroll
        for (int i = 0; i < 4; i++) {
            int idx = g + i * 32768;                                  // 0..131071
            int e = __ldg(&e_space[idx]);
            const char* p = (const char*)(ent_emb + (size_t)e * ENT_D);
#pragma unroll
            for (int j = 0; j < 8; j++)
                asm volatile("prefetch.global.L2 [%0];" :: "l"(p + j * 128));
        }
    }

    // A-load geometry
    int ar = tid >> 3;
    int ac = tid & 7;
    int arow = brow + ar;
    int ce = 0, rr = 0;
    const float* Ah = nullptr;
    if (FIRST) { ce = cur[arow]; rr = qr[arow]; }
    else       { Ah = (const float*)g_H; }

    auto loadA = [&](int k0) -> float4 {
        int kk = k0 + ac * 4;
        if (FIRST) {
            if (kk < ENT_D)
                return *reinterpret_cast<const float4*>(ent_emb + (size_t)ce * ENT_D + kk);
            if (kk < ENT_D + HIST_D)
                return *reinterpret_cast<const float4*>(hist + (size_t)arow * HIST_D + (kk - ENT_D));
            return *reinterpret_cast<const float4*>(rel_emb + (size_t)rr * REL_D + (kk - ENT_D - HIST_D));
        } else {
            return *reinterpret_cast<const float4*>(Ah + (size_t)arow * ACT_DIM + kk);
        }
    };

    int bk0 = tid >> 4;
    int bc0 = tid & 15;
    auto loadB = [&](int k0, int it) -> float4 {
        int kk = bk0 + it * 16;
        return *reinterpret_cast<const float4*>(&W[(size_t)(k0 + kk) * N + bcol + bc0 * 4]);
    };
    auto storeTile = [&](int buf, float4 av, float4 bv0, float4 bv1) {
        As[buf][ar][ac * 4 + 0] = to_tf32(av.x);
        As[buf][ar][ac * 4 + 1] = to_tf32(av.y);
        As[buf][ar][ac * 4 + 2] = to_tf32(av.z);
        As[buf][ar][ac * 4 + 3] = to_tf32(av.w);
        Bs[buf][bk0     ][bc0 * 4 + 0] = to_tf32(bv0.x);
        Bs[buf][bk0     ][bc0 * 4 + 1] = to_tf32(bv0.y);
        Bs[buf][bk0     ][bc0 * 4 + 2] = to_tf32(bv0.z);
        Bs[buf][bk0     ][bc0 * 4 + 3] = to_tf32(bv0.w);
        Bs[buf][bk0 + 16][bc0 * 4 + 0] = to_tf32(bv1.x);
        Bs[buf][bk0 + 16][bc0 * 4 + 1] = to_tf32(bv1.y);
        Bs[buf][bk0 + 16][bc0 * 4 + 2] = to_tf32(bv1.z);
        Bs[buf][bk0 + 16][bc0 * 4 + 3] = to_tf32(bv1.w);
    };

    float c[2][4];
#pragma unroll
    for (int j = 0; j < 2; j++)
#pragma unroll
        for (int i = 0; i < 4; i++) c[j][i] = 0.f;

    {
        float4 av  = loadA(0);
        float4 bv0 = loadB(0, 0);
        float4 bv1 = loadB(0, 1);
        storeTile(0, av, bv0, bv1);
    }
    __syncthreads();

    const int NIT = K / 32;
    for (int it = 0; it < NIT; it++) {
        int cb = it & 1, nb = cb ^ 1;
        float4 av, bv0, bv1;
        bool more = (it + 1 < NIT);
        if (more) {
            int k0 = (it + 1) * 32;
            av  = loadA(k0);
            bv0 = loadB(k0, 0);
            bv1 = loadB(k0, 1);
        }

#pragma unroll
        for (int ks = 0; ks < 4; ks++) {
            int kb = ks * 8;
            uint32_t a0 = __float_as_uint(As[cb][warp_m + group    ][kb + tig    ]);
            uint32_t a1 = __float_as_uint(As[cb][warp_m + group + 8][kb + tig    ]);
            uint32_t a2 = __float_as_uint(As[cb][warp_m + group    ][kb + tig + 4]);
            uint32_t a3 = __float_as_uint(As[cb][warp_m + group + 8][kb + tig + 4]);
#pragma unroll
            for (int j = 0; j < 2; j++) {
                int col = warp_n + j * 8 + group;
                uint32_t b0 = __float_as_uint(Bs[cb][kb + tig    ][col]);
                uint32_t b1 = __float_as_uint(Bs[cb][kb + tig + 4][col]);
                asm volatile(
                    "mma.sync.aligned.m16n8k8.row.col.f32.tf32.tf32.f32 "
                    "{%0,%1,%2,%3}, {%4,%5,%6,%7}, {%8,%9}, {%0,%1,%2,%3};"
                    : "+f"(c[j][0]), "+f"(c[j][1]), "+f"(c[j][2]), "+f"(c[j][3])
                    : "r"(a0), "r"(a1), "r"(a2), "r"(a3), "r"(b0), "r"(b1));
            }
        }

        if (more) storeTile(nb, av, bv0, bv1);
        __syncthreads();
    }

#pragma unroll
    for (int j = 0; j < 2; j++) {
        int row = brow + warp_m + group;
        int col = bcol + warp_n + j * 8 + 2 * tig;
        float bc0 = bias[col], bc1 = bias[col + 1];
        float v00 = c[j][0] + bc0, v01 = c[j][1] + bc1;
        float v10 = c[j][2] + bc0, v11 = c[j][3] + bc1;
        if (FIRST) {
            v00 = fmaxf(v00, 0.f); v01 = fmaxf(v01, 0.f);
            v10 = fmaxf(v10, 0.f); v11 = fmaxf(v11, 0.f);
        }
        C[(size_t)row * N + col]           = v00;
        C[(size_t)row * N + col + 1]       = v01;
        C[(size_t)(row + 8) * N + col]     = v10;
        C[(size_t)(row + 8) * N + col + 1] = v11;
    }
}

// ---------------------------------------------------------------------------
// Scores: 8 threads/action, 32 actions/block, grid (8,B).
// Ent rows should now be L2-resident thanks to the GEMM1 prefetch.
// ---------------------------------------------------------------------------
__global__ void scores_kernel(const int* __restrict__ r_space,
                              const int* __restrict__ e_space,
                              const int* __restrict__ amask,
                              const float* __restrict__ rel_emb,
                              const float* __restrict__ ent_emb) {
    int b   = blockIdx.y;
    int tid = threadIdx.x;
    int al  = tid >> 3;
    int sub = tid & 7;
    int a   = blockIdx.x * 32 + al;

    __shared__ float x2s[ACT_DIM];
    x2s[tid]       = g_X2[(size_t)b * ACT_DIM + tid];
    x2s[tid + 256] = g_X2[(size_t)b * ACT_DIM + tid + 256];

    int r = r_space[b * NACT + a];
    int e = e_space[b * NACT + a];
    const float4* rp4 = reinterpret_cast<const float4*>(rel_emb + (size_t)r * REL_D);
    const float4* ep4 = reinterpret_cast<const float4*>(ent_emb + (size_t)e * ENT_D);

    float4 ev[8];
#pragma unroll
    for (int i = 0; i < 8; i++) ev[i] = ep4[sub + i * 8];

    float4 rv[8];
#pragma unroll
    for (int i = 0; i < 8; i++) rv[i] = rp4[sub + i * 8];

    __syncthreads();
    const float4* xa = reinterpret_cast<const float4*>(x2s);

    float s = 0.f;
#pragma unroll
    for (int i = 0; i < 8; i++) {
        float4 xv = xa[sub + i * 8];
        s += rv[i].x * xv.x + rv[i].y * xv.y + rv[i].z * xv.z + rv[i].w * xv.w;
    }
#pragma unroll
    for (int i = 0; i < 8; i++) {
        float4 xw = xa[64 + sub + i * 8];
        s += ev[i].x * xw.x + ev[i].y * xw.y + ev[i].z * xw.z + ev[i].w * xw.w;
    }

    s += __shfl_xor_sync(0xffffffffu, s, 1);
    s += __shfl_xor_sync(0xffffffffu, s, 2);
    s += __shfl_xor_sync(0xffffffffu, s, 4);

    if (sub == 0) {
        float m = (float)amask[b * NACT + a];
        g_SC[b * NACT + a] = s - (1.0f - m) * HUGE_F;
    }
}

// ---------------------------------------------------------------------------
// Softmax + entropy per row. 128 threads, 2 elements each (one sync level less
// work per block; 4 warps).
// ---------------------------------------------------------------------------
__global__ void softmax_kernel(float* __restrict__ out) {
    int b    = blockIdx.x;
    int tid  = threadIdx.x;          // 0..127
    int lane = tid & 31;
    int warp = tid >> 5;             // 0..3
    __shared__ float red[4];

    float v0 = g_SC[b * NACT + tid];
    float v1 = g_SC[b * NACT + tid + 128];

    float m = fmaxf(v0, v1);
#pragma unroll
    for (int o = 16; o; o >>= 1) m = fmaxf(m, __shfl_xor_sync(0xffffffffu, m, o));
    if (lane == 0) red[warp] = m;
    __syncthreads();
    float mx = fmaxf(fmaxf(red[0], red[1]), fmaxf(red[2], red[3]));
    __syncthreads();

    float e0 = expf(v0 - mx), e1 = expf(v1 - mx);
    float s = e0 + e1;
#pragma unroll
    for (int o = 16; o; o >>= 1) s += __shfl_xor_sync(0xffffffffu, s, o);
    if (lane == 0) red[warp] = s;
    __syncthreads();
    float tot = red[0] + red[1] + red[2] + red[3];
    __syncthreads();

    float inv = 1.0f / tot;
    float p0 = e0 * inv, p1 = e1 * inv;
    out[(size_t)b * NACT + tid]       = p0;
    out[(size_t)b * NACT + tid + 128] = p1;

    float et = -p0 * logf(p0 + EPS_F) - p1 * logf(p1 + EPS_F);
#pragma unroll
    for (int o = 16; o; o >>= 1) et += __shfl_xor_sync(0xffffffffu, et, o);
    if (lane == 0) red[warp] = et;
    __syncthreads();
    if (tid == 0)
        out[(size_t)BATCH * NACT + b] = red[0] + red[1] + red[2] + red[3];
}

// ---------------------------------------------------------------------------
extern "C" void kernel_launch(void* const* d_in, const int* in_sizes, int n_in,
                              void* d_out, int out_size) {
    const int*   cur     = (const int*)  d_in[0];
    const int*   qr      = (const int*)  d_in[1];
    const float* hist    = (const float*)d_in[2];
    const int*   r_space = (const int*)  d_in[3];
    const int*   e_space = (const int*)  d_in[4];
    const int*   amask   = (const int*)  d_in[5];
    const float* ent_emb = (const float*)d_in[6];
    const float* rel_emb = (const float*)d_in[7];
    const float* W1      = (const float*)d_in[8];
    const float* b1      = (const float*)d_in[9];
    const float* W2      = (const float*)d_in[10];
    const float* b2      = (const float*)d_in[11];
    float* out = (float*)d_out;

    dim3 ggrid(ACT_DIM / 64, BATCH / 32);    // 8 x 16 = 128 blocks
    mma_gemm_kernel<IN_DIM,  true ><<<ggrid, 256>>>(W1, b1, cur, qr, hist, ent_emb, rel_emb, e_space);
    mma_gemm_kernel<ACT_DIM, false><<<ggrid, 256>>>(W2, b2, cur, qr, hist, ent_emb, rel_emb, e_space);

    dim3 sgrid(NACT / 32, BATCH);            // 8 x 512 = 4096 blocks
    scores_kernel<<<sgrid, 256>>>(r_space, e_space, amask, rel_emb, ent_emb);

    softmax_kernel<<<BATCH, 128>>>(out);
}